// round 5
// baseline (speedup 1.0000x reference)
#include <cuda_runtime.h>
#include <stdint.h>

#define NALGOS 64
#define NTASKS 1024
#define LXN    512
#define FULLMASK 0xffffffffu

// Scratch (no allocations allowed).
// g_G[s*512 + t] = TM[lx[s]][lx[t]]
__device__ float g_G[LXN * LXN];
__device__ float g_u[NALGOS * LXN];
__device__ int   g_flag[NALGOS * 32];     // padded: one 128B line per algo

// 2*sigmoid(z) - 1 == tanh(z/2): single MUFU.TANH, abs err ~2^-11.
__device__ __forceinline__ float tanh_fast(float x) {
    float y;
    asm("tanh.approx.f32 %0, %1;" : "=f"(y) : "f"(x));
    return y;
}
__device__ __forceinline__ void st_release_gpu(int* p, int v) {
    asm volatile("st.release.gpu.global.u32 [%0], %1;" :: "l"(p), "r"(v) : "memory");
}
__device__ __forceinline__ int ld_acquire_gpu(const int* p) {
    int v;
    asm volatile("ld.acquire.gpu.global.u32 %0, [%1];" : "=r"(v) : "l"(p) : "memory");
    return v;
}
__device__ __forceinline__ float ldcg_f32(const float* p) {
    float v;
    asm volatile("ld.global.cg.f32 %0, [%1];" : "=f"(v) : "l"(p) : "memory");
    return v;
}
__device__ __forceinline__ void stcg_f32(float* p, float v) {
    asm volatile("st.global.cg.f32 [%0], %1;" :: "l"(p), "f"(v) : "memory");
}

// ---------------------------------------------------------------------------
// Kernel 0: G[s][t] = TM[lx[s]][lx[t]]; also reset per-algo progress flags.
// ---------------------------------------------------------------------------
__global__ void build_G(const int* __restrict__ lx, const float* __restrict__ TM) {
    int s = blockIdx.x;
    int t = threadIdx.x;
    if (s == 0 && t < NALGOS) g_flag[t * 32] = 0;
    int row = __ldg(lx + s);
    int col = __ldg(lx + t);
    g_G[s * LXN + t] = __ldg(TM + row * NTASKS + col);
}

// ---------------------------------------------------------------------------
// Fused kernel: 320 blocks x 256 threads, ALL co-resident (37.9KB smem -> 6/SM,
// launch_bounds(256,4) -> regs cap; need only 2.2/SM).
//   blocks 0..63    : phase1 blocked-scan chain for algo a = bid.
//                     Publishes g_u chunk-by-chunk: bulk warp 1 copies the
//                     32 u's (st.cg), per-lane __threadfence, syncwarp, then
//                     lane0 st.release flag[a] = c+1.  Off the chain path.
//   blocks 64..319  : phase2 for (algo a, j-tile of 256).  Before chunk c,
//                     warp-0 lanes spin ld.acquire flag[a] > c (nanosleep
//                     backoff), stage the 32 u's via ld.cg, syncthreads.
// Total ~= build_G + max(phase1, phase2) instead of the sum.
// ---------------------------------------------------------------------------
__global__ void __launch_bounds__(256, 4) fused(
    const int* __restrict__ lx, const float* __restrict__ diff,
    const float* __restrict__ eff_, const float* __restrict__ mem_,
    const float* __restrict__ boost_, const float* __restrict__ TM,
    float* __restrict__ out) {

    __shared__ float u_sh[LXN];
    __shared__ float big[8 * 32 * 33];   // p1: c2_sh[512] + Bnext[2][32] | p2: tbuf
    __shared__ int   off_sh[LXN];

    int bid = blockIdx.x;
    int tid = threadIdx.x;
    int w = tid >> 5, l = tid & 31;

    if (bid < NALGOS) {
        // ================= PHASE 1 (chain) =================
        int a = bid;
        float* c2_sh = big;                 // [512]
        float* Bnext = big + LXN;           // [2][32]

        float mem = __ldg(mem_ + a), eff = __ldg(eff_ + a), boost = __ldg(boost_ + a);
        float m2 = mem * mem, m4 = m2 * m2, m8 = m4 * m4, m16 = m8 * m8;
        float M32 = m16 * m16;

        for (int t = tid; t < LXN; t += 256)
            c2_sh[t] = 0.5f / __ldg(diff + __ldg(lx + t));
        __syncthreads();

        if (w == 0) {
            // ---- chain warp ----
            float racc = 0.0f, racc2 = 0.0f;
            float c2l = c2_sh[l];
            float u_val = eff;

#pragma unroll 1
            for (int c = 0; c < 16; ++c) {
                int t0 = c * 32;
                const float* gArow = g_G + t0 + l;
                const float* gBrow = g_G + t0 + 32 + l;
                bool hasB = (c < 15);

                float gA[8], gB[8];
#pragma unroll
                for (int q = 0; q < 8; ++q) {
                    gA[q] = __ldg(gArow + (t0 + q) * LXN);
                    gB[q] = hasB ? __ldg(gBrow + (t0 + q) * LXN) : 0.0f;
                }
#pragma unroll 8
                for (int k = 0; k < 32; ++k) {
                    int q = k & 7;
                    if (l == k)
                        u_val = fmaf(tanh_fast(racc * c2l), boost, eff);
                    float u = __shfl_sync(FULLMASK, u_val, k);
                    if (l == k) u_sh[t0 + k] = u;
                    racc  = fmaf(racc,  mem, gA[q] * u);
                    racc2 = fmaf(racc2, mem, gB[q] * u);
                    if (k + 8 < 32) {
                        gA[q] = __ldg(gArow + (t0 + k + 8) * LXN);
                        gB[q] = hasB ? __ldg(gBrow + (t0 + k + 8) * LXN) : 0.0f;
                    }
                }
                __syncthreads();                  // chunk c u_sh complete
                if (c < 15) {
                    racc  = fmaf(Bnext[((c + 1) & 1) * 32 + l], M32, racc2);
                    racc2 = 0.0f;
                    c2l   = c2_sh[t0 + 32 + l];
                }
            }
        } else {
            // ---- bulk warps 1..7 ----
            int base0 = (w - 1) * 32 + l;
            bool has3 = (base0 + 448 < LXN);
            float R0 = 0.0f, R1 = 0.0f, R2v = 0.0f;

#pragma unroll 1
            for (int c = 0; c < 16; ++c) {
                if (c >= 1) {
                    int s0 = (c - 1) * 32;
                    const float* g0 = g_G + base0;
#pragma unroll 8
                    for (int k = 0; k < 32; ++k) {
                        float u = u_sh[s0 + k];
                        const float* gr = g0 + (s0 + k) * LXN;
                        R0 = fmaf(R0, mem, __ldg(gr) * u);
                        R1 = fmaf(R1, mem, __ldg(gr + 224) * u);
                        if (has3) R2v = fmaf(R2v, mem, __ldg(gr + 448) * u);
                    }
                }
                int b = c + 1;
                if (b <= 15 && (w - 1) == (b % 7)) {
                    int i = b / 7;
                    float Rv = (i == 0) ? R0 : (i == 1) ? R1 : R2v;
                    Bnext[(b & 1) * 32 + l] = Rv;
                }
                __syncthreads();                  // matches chain barrier c
                // publish chunk c to consumers (off the chain's critical path)
                if (w == 1) {
                    stcg_f32(g_u + a * LXN + c * 32 + l, u_sh[c * 32 + l]);
                    __threadfence();
                    __syncwarp();
                    if (l == 0) st_release_gpu(g_flag + a * 32, c + 1);
                }
            }
        }
    } else {
        // ================= PHASE 2 =================
        int b  = bid - NALGOS;
        int a  = b >> 2;                     // 64 algos
        int jb = b & 3;                      // 4 j-tiles of 256
        int j  = jb * 256 + tid;
        float* tbuf = big + w * (32 * 33);   // per-warp 32x33 transpose buffer

        for (int i = tid; i < LXN; i += 256)
            off_sh[i] = __ldg(lx + i) << 10;

        float mem = __ldg(mem_ + a);
        float c2  = 0.5f / __ldg(diff + j);
        float r   = 0.0f;

        unsigned obase = (unsigned)(a * NTASKS + j) * 513u;
        out[obase] = 0.0f;
        unsigned tbase = (unsigned)(a * NTASKS + jb * 256 + w * 32) * 513u
                         + 1u + (unsigned)l;
        const int* fp = g_flag + a * 32;
        __syncthreads();                      // off_sh ready

        for (int c = 0; c < 16; ++c) {
            if (tid < 32) {
                while (ld_acquire_gpu(fp) <= c) __nanosleep(64);
                u_sh[c * 32 + tid] = ldcg_f32(g_u + a * LXN + c * 32 + tid);
            }
            __syncthreads();
#pragma unroll 8
            for (int k = 0; k < 32; ++k) {
                int s = c * 32 + k;
                float val = __ldg(TM + off_sh[s] + j);
                r = fmaf(r, mem, val * u_sh[s]);
                tbuf[l * 33 + k] = tanh_fast(r * c2);
            }
            __syncwarp();
            unsigned ob = tbase + (unsigned)(c * 32);
#pragma unroll 8
            for (int row = 0; row < 32; ++row)
                out[ob + (unsigned)row * 513u] = tbuf[row * 33 + l];
            __syncwarp();
        }
    }
}

// ---------------------------------------------------------------------------
extern "C" void kernel_launch(void* const* d_in, const int* in_sizes, int n_in,
                              void* d_out, int out_size) {
    const int*   lx    = (const int*)  d_in[0];
    const float* TM    = (const float*)d_in[1];
    const float* diff  = (const float*)d_in[2];
    const float* eff   = (const float*)d_in[3];
    const float* mem   = (const float*)d_in[4];
    const float* boost = (const float*)d_in[5];
    float* out = (float*)d_out;

    build_G<<<LXN, LXN>>>(lx, TM);
    fused<<<NALGOS + NALGOS * 4, 256>>>(lx, diff, eff, mem, boost, TM, out);
}

// round 6
// speedup vs baseline: 1.3528x; 1.3528x over previous
#include <cuda_runtime.h>
#include <stdint.h>

#define NALGOS 64
#define NTASKS 1024
#define LXN    512
#define FULLMASK 0xffffffffu

// Scratch (no allocations allowed).
// g_G[s*512 + t] = TM[lx[s]][lx[t]]
__device__ float g_G[LXN * LXN];
__device__ float g_u[NALGOS * LXN];
__device__ int   g_flag[NALGOS * 32];     // padded: one 128B line per algo

// 2*sigmoid(z) - 1 == tanh(z/2): single MUFU.TANH, abs err ~2^-11.
__device__ __forceinline__ float tanh_fast(float x) {
    float y;
    asm("tanh.approx.f32 %0, %1;" : "=f"(y) : "f"(x));
    return y;
}
__device__ __forceinline__ void st_release_gpu(int* p, int v) {
    asm volatile("st.release.gpu.global.u32 [%0], %1;" :: "l"(p), "r"(v) : "memory");
}
__device__ __forceinline__ int ld_acquire_gpu(const int* p) {
    int v;
    asm volatile("ld.acquire.gpu.global.u32 %0, [%1];" : "=r"(v) : "l"(p) : "memory");
    return v;
}
__device__ __forceinline__ float ldcg_f32(const float* p) {
    float v;
    asm volatile("ld.global.cg.f32 %0, [%1];" : "=f"(v) : "l"(p) : "memory");
    return v;
}
__device__ __forceinline__ void stcg_f32(float* p, float v) {
    asm volatile("st.global.cg.f32 [%0], %1;" :: "l"(p), "f"(v) : "memory");
}

// ---------------------------------------------------------------------------
// Kernel 0: G[s][t] = TM[lx[s]][lx[t]]; also reset per-algo progress flags.
// ---------------------------------------------------------------------------
__global__ void build_G(const int* __restrict__ lx, const float* __restrict__ TM) {
    int s = blockIdx.x;
    int t = threadIdx.x;
    if (s == 0 && t < NALGOS) g_flag[t * 32] = 0;
    int row = __ldg(lx + s);
    int col = __ldg(lx + t);
    g_G[s * LXN + t] = __ldg(TM + row * NTASKS + col);
}

// ---------------------------------------------------------------------------
// Fused kernel: 320 co-resident blocks.
//   blocks 0..63   : phase1 blocked-scan for algo a. Chain warp is now fully
//                    BRANCH-FREE: all lanes compute the tanh candidate every
//                    step; shfl selects the owner lane's value. No BSSY/BSYNC,
//                    no divergent region on the 512-long serial chain.
//   blocks 64..319 : phase2 consumers, spin-acquire on per-algo chunk flags.
// ---------------------------------------------------------------------------
__global__ void __launch_bounds__(256, 4) fused(
    const int* __restrict__ lx, const float* __restrict__ diff,
    const float* __restrict__ eff_, const float* __restrict__ mem_,
    const float* __restrict__ boost_, const float* __restrict__ TM,
    float* __restrict__ out) {

    __shared__ float u_sh[LXN];
    __shared__ float big[8 * 32 * 33];   // p1: c2_sh[512] + Bnext[2][32] | p2: tbuf
    __shared__ int   off_sh[LXN];

    int bid = blockIdx.x;
    int tid = threadIdx.x;
    int w = tid >> 5, l = tid & 31;

    if (bid < NALGOS) {
        // ================= PHASE 1 =================
        int a = bid;
        float* c2_sh = big;                 // [512]
        float* Bnext = big + LXN;           // [2][32]

        float mem = __ldg(mem_ + a), eff = __ldg(eff_ + a), boost = __ldg(boost_ + a);
        float m2 = mem * mem, m4 = m2 * m2, m8 = m4 * m4, m16 = m8 * m8;
        float M32 = m16 * m16;

        for (int t = tid; t < LXN; t += 256)
            c2_sh[t] = 0.5f / __ldg(diff + __ldg(lx + t));
        __syncthreads();

        if (w == 0) {
            // ---- chain warp: branch-free serial recursion ----
            float racc = 0.0f, racc2 = 0.0f;
            float c2l = c2_sh[l];
            float my_u = 0.0f;

#pragma unroll 1
            for (int c = 0; c < 16; ++c) {
                int t0 = c * 32;
                const float* gArow = g_G + t0 + l;
                const float* gBrow = g_G + t0 + 32 + l;
                bool hasB = (c < 15);

                float gA[8], gB[8];
#pragma unroll
                for (int q = 0; q < 8; ++q) {
                    gA[q] = __ldg(gArow + (t0 + q) * LXN);
                    gB[q] = hasB ? __ldg(gBrow + (t0 + q) * LXN) : 0.0f;
                }
#pragma unroll
                for (int k = 0; k < 32; ++k) {
                    int q = k & 7;
                    // ALL lanes compute; only lane k's value is meaningful.
                    float cand = fmaf(tanh_fast(racc * c2l), boost, eff);
                    float u = __shfl_sync(FULLMASK, cand, k);
                    my_u = (l == k) ? u : my_u;          // FSEL, branch-free
                    racc  = fmaf(racc,  mem, gA[q] * u);
                    racc2 = fmaf(racc2, mem, gB[q] * u);
                    if (k + 8 < 32) {                    // compile-time per instance
                        gA[q] = __ldg(gArow + (t0 + k + 8) * LXN);
                        gB[q] = hasB ? __ldg(gBrow + (t0 + k + 8) * LXN) : 0.0f;
                    }
                }
                u_sh[t0 + l] = my_u;                     // unconditional STS
                __syncthreads();                         // chunk c complete
                if (c < 15) {
                    racc  = fmaf(Bnext[((c + 1) & 1) * 32 + l], M32, racc2);
                    racc2 = 0.0f;
                    c2l   = c2_sh[t0 + 32 + l];
                }
            }
        } else {
            // ---- bulk warps 1..7 (one chunk behind) ----
            int base0 = (w - 1) * 32 + l;
            bool has3 = (base0 + 448 < LXN);             // warps 1,2 only (uniform)
            float R0 = 0.0f, R1 = 0.0f, R2v = 0.0f;

#pragma unroll 1
            for (int c = 0; c < 16; ++c) {
                if (c >= 1) {
                    int s0 = (c - 1) * 32;
                    const float* g0 = g_G + base0;
#pragma unroll 8
                    for (int k = 0; k < 32; ++k) {
                        float u = u_sh[s0 + k];
                        const float* gr = g0 + (s0 + k) * LXN;
                        R0 = fmaf(R0, mem, __ldg(gr) * u);
                        R1 = fmaf(R1, mem, __ldg(gr + 224) * u);
                        if (has3) R2v = fmaf(R2v, mem, __ldg(gr + 448) * u);
                    }
                }
                int b = c + 1;
                if (b <= 15 && (w - 1) == (b % 7)) {
                    int i = b / 7;
                    float Rv = (i == 0) ? R0 : (i == 1) ? R1 : R2v;
                    Bnext[(b & 1) * 32 + l] = Rv;
                }
                __syncthreads();                         // matches chain barrier c
                // publish chunk c to consumers (off the chain's critical path)
                if (w == 1) {
                    stcg_f32(g_u + a * LXN + c * 32 + l, u_sh[c * 32 + l]);
                    __threadfence();
                    __syncwarp();
                    if (l == 0) st_release_gpu(g_flag + a * 32, c + 1);
                }
            }
        }
    } else {
        // ================= PHASE 2 =================
        int b  = bid - NALGOS;
        int a  = b >> 2;
        int jb = b & 3;
        int j  = jb * 256 + tid;
        float* tbuf = big + w * (32 * 33);

        for (int i = tid; i < LXN; i += 256)
            off_sh[i] = __ldg(lx + i) << 10;

        float mem = __ldg(mem_ + a);
        float c2  = 0.5f / __ldg(diff + j);
        float r   = 0.0f;

        unsigned obase = (unsigned)(a * NTASKS + j) * 513u;
        out[obase] = 0.0f;
        unsigned tbase = (unsigned)(a * NTASKS + jb * 256 + w * 32) * 513u
                         + 1u + (unsigned)l;
        const int* fp = g_flag + a * 32;
        __syncthreads();

        for (int c = 0; c < 16; ++c) {
            if (tid < 32) {
                while (ld_acquire_gpu(fp) <= c) __nanosleep(64);
                u_sh[c * 32 + tid] = ldcg_f32(g_u + a * LXN + c * 32 + tid);
            }
            __syncthreads();
#pragma unroll 8
            for (int k = 0; k < 32; ++k) {
                int s = c * 32 + k;
                float val = __ldg(TM + off_sh[s] + j);
                r = fmaf(r, mem, val * u_sh[s]);
                tbuf[l * 33 + k] = tanh_fast(r * c2);
            }
            __syncwarp();
            unsigned ob = tbase + (unsigned)(c * 32);
#pragma unroll 8
            for (int row = 0; row < 32; ++row)
                out[ob + (unsigned)row * 513u] = tbuf[row * 33 + l];
            __syncwarp();
        }
    }
}

// ---------------------------------------------------------------------------
extern "C" void kernel_launch(void* const* d_in, const int* in_sizes, int n_in,
                              void* d_out, int out_size) {
    const int*   lx    = (const int*)  d_in[0];
    const float* TM    = (const float*)d_in[1];
    const float* diff  = (const float*)d_in[2];
    const float* eff   = (const float*)d_in[3];
    const float* mem   = (const float*)d_in[4];
    const float* boost = (const float*)d_in[5];
    float* out = (float*)d_out;

    build_G<<<LXN, LXN>>>(lx, TM);
    fused<<<NALGOS + NALGOS * 4, 256>>>(lx, diff, eff, mem, boost, TM, out);
}

// round 7
// speedup vs baseline: 2.6667x; 1.9713x over previous
#include <cuda_runtime.h>
#include <stdint.h>

#define NALGOS 64
#define NTASKS 1024
#define LXN    512
#define FULLMASK 0xffffffffu

// Scratch (no allocations allowed).
// g_G[s*512 + t] = TM[lx[s]][lx[t]]
__device__ float g_G[LXN * LXN];
__device__ float g_u[NALGOS * LXN];
__device__ int   g_flag[NALGOS * 128];    // 4 padded copies (32 ints apart) per algo

// 2*sigmoid(z) - 1 == tanh(z/2): single MUFU.TANH, abs err ~2^-11.
__device__ __forceinline__ float tanh_fast(float x) {
    float y;
    asm("tanh.approx.f32 %0, %1;" : "=f"(y) : "f"(x));
    return y;
}
__device__ __forceinline__ void st_release_gpu(int* p, int v) {
    asm volatile("st.release.gpu.global.u32 [%0], %1;" :: "l"(p), "r"(v) : "memory");
}
__device__ __forceinline__ int ld_acquire_gpu(const int* p) {
    int v;
    asm volatile("ld.acquire.gpu.global.u32 %0, [%1];" : "=r"(v) : "l"(p) : "memory");
    return v;
}
__device__ __forceinline__ float ldcg_f32(const float* p) {
    float v;
    asm volatile("ld.global.cg.f32 %0, [%1];" : "=f"(v) : "l"(p) : "memory");
    return v;
}
__device__ __forceinline__ void stcg_f32(float* p, float v) {
    asm volatile("st.global.cg.f32 [%0], %1;" :: "l"(p), "f"(v) : "memory");
}
__device__ __forceinline__ void stcs_f32(float* p, float v) {
    asm volatile("st.global.cs.f32 [%0], %1;" :: "l"(p), "f"(v) : "memory");
}

// ---------------------------------------------------------------------------
// Kernel 0: G[s][t] = TM[lx[s]][lx[t]]; also reset per-algo progress flags.
// ---------------------------------------------------------------------------
__global__ void build_G(const int* __restrict__ lx, const float* __restrict__ TM) {
    int s = blockIdx.x;
    int t = threadIdx.x;
    if (s == 0 && t < NALGOS * 4) g_flag[(t >> 2) * 128 + (t & 3) * 32] = 0;
    int row = __ldg(lx + s);
    int col = __ldg(lx + t);
    g_G[s * LXN + t] = __ldg(TM + row * NTASKS + col);
}

// ---------------------------------------------------------------------------
// Fused kernel: 320 co-resident blocks (4/SM cap, 37.9KB smem).
//   blocks 0..63   : phase1 blocked-scan chain (branch-free, unchanged R6).
//                    Publishes u chunk-by-chunk; flags replicated x4.
//   blocks 64..319 : phase2. Per chunk: 32 TM LDGs prefetched into registers
//                    BEFORE the flag spin (wait hides L2 latency), tight
//                    acquire-poll on a per-block flag copy (no nanosleep),
//                    compute entirely from registers, streaming st.cs out.
// ---------------------------------------------------------------------------
__global__ void __launch_bounds__(256, 4) fused(
    const int* __restrict__ lx, const float* __restrict__ diff,
    const float* __restrict__ eff_, const float* __restrict__ mem_,
    const float* __restrict__ boost_, const float* __restrict__ TM,
    float* __restrict__ out) {

    __shared__ float u_sh[LXN];
    __shared__ float big[8 * 32 * 33];   // p1: c2_sh[512]+Bnext[2][32] | p2: tbuf
    __shared__ int   off_sh[LXN];

    int bid = blockIdx.x;
    int tid = threadIdx.x;
    int w = tid >> 5, l = tid & 31;

    if (bid < NALGOS) {
        // ================= PHASE 1 =================
        int a = bid;
        float* c2_sh = big;
        float* Bnext = big + LXN;

        float mem = __ldg(mem_ + a), eff = __ldg(eff_ + a), boost = __ldg(boost_ + a);
        float m2 = mem * mem, m4 = m2 * m2, m8 = m4 * m4, m16 = m8 * m8;
        float M32 = m16 * m16;

        for (int t = tid; t < LXN; t += 256)
            c2_sh[t] = 0.5f / __ldg(diff + __ldg(lx + t));
        __syncthreads();

        if (w == 0) {
            // ---- chain warp: branch-free serial recursion (R6-proven) ----
            float racc = 0.0f, racc2 = 0.0f;
            float c2l = c2_sh[l];
            float my_u = 0.0f;

#pragma unroll 1
            for (int c = 0; c < 16; ++c) {
                int t0 = c * 32;
                const float* gArow = g_G + t0 + l;
                const float* gBrow = g_G + t0 + 32 + l;
                bool hasB = (c < 15);

                float gA[8], gB[8];
#pragma unroll
                for (int q = 0; q < 8; ++q) {
                    gA[q] = __ldg(gArow + (t0 + q) * LXN);
                    gB[q] = hasB ? __ldg(gBrow + (t0 + q) * LXN) : 0.0f;
                }
#pragma unroll
                for (int k = 0; k < 32; ++k) {
                    int q = k & 7;
                    float cand = fmaf(tanh_fast(racc * c2l), boost, eff);
                    float u = __shfl_sync(FULLMASK, cand, k);
                    my_u = (l == k) ? u : my_u;
                    racc  = fmaf(racc,  mem, gA[q] * u);
                    racc2 = fmaf(racc2, mem, gB[q] * u);
                    if (k + 8 < 32) {
                        gA[q] = __ldg(gArow + (t0 + k + 8) * LXN);
                        gB[q] = hasB ? __ldg(gBrow + (t0 + k + 8) * LXN) : 0.0f;
                    }
                }
                u_sh[t0 + l] = my_u;
                __syncthreads();
                if (c < 15) {
                    racc  = fmaf(Bnext[((c + 1) & 1) * 32 + l], M32, racc2);
                    racc2 = 0.0f;
                    c2l   = c2_sh[t0 + 32 + l];
                }
            }
        } else {
            // ---- bulk warps 1..7 ----
            int base0 = (w - 1) * 32 + l;
            bool has3 = (base0 + 448 < LXN);
            float R0 = 0.0f, R1 = 0.0f, R2v = 0.0f;

#pragma unroll 1
            for (int c = 0; c < 16; ++c) {
                if (c >= 1) {
                    int s0 = (c - 1) * 32;
                    const float* g0 = g_G + base0;
#pragma unroll 8
                    for (int k = 0; k < 32; ++k) {
                        float u = u_sh[s0 + k];
                        const float* gr = g0 + (s0 + k) * LXN;
                        R0 = fmaf(R0, mem, __ldg(gr) * u);
                        R1 = fmaf(R1, mem, __ldg(gr + 224) * u);
                        if (has3) R2v = fmaf(R2v, mem, __ldg(gr + 448) * u);
                    }
                }
                int b = c + 1;
                if (b <= 15 && (w - 1) == (b % 7)) {
                    int i = b / 7;
                    float Rv = (i == 0) ? R0 : (i == 1) ? R1 : R2v;
                    Bnext[(b & 1) * 32 + l] = Rv;
                }
                __syncthreads();
                // publish chunk c (off the chain's critical path)
                if (w == 1) {
                    stcg_f32(g_u + a * LXN + c * 32 + l, u_sh[c * 32 + l]);
                    __threadfence();
                    __syncwarp();
                    if (l < 4) st_release_gpu(g_flag + a * 128 + l * 32, c + 1);
                }
            }
        }
    } else {
        // ================= PHASE 2 =================
        int b  = bid - NALGOS;
        int a  = b >> 2;
        int jb = b & 3;
        int j  = jb * 256 + tid;
        float* tbuf = big + w * (32 * 33);

        for (int i = tid; i < LXN; i += 256)
            off_sh[i] = __ldg(lx + i) << 10;

        float mem = __ldg(mem_ + a);
        float c2  = 0.5f / __ldg(diff + j);
        float r   = 0.0f;

        unsigned obase = (unsigned)(a * NTASKS + j) * 513u;
        stcs_f32(out + obase, 0.0f);
        unsigned tbase = (unsigned)(a * NTASKS + jb * 256 + w * 32) * 513u
                         + 1u + (unsigned)l;
        const int* fp = g_flag + a * 128 + jb * 32;   // private flag copy
        const float* TMj = TM + j;
        __syncthreads();

        for (int c = 0; c < 16; ++c) {
            // 1) prefetch this chunk's 32 TM values (independent of the flag)
            float v[32];
#pragma unroll
            for (int k = 0; k < 32; ++k)
                v[k] = __ldg(TMj + off_sh[c * 32 + k]);
            // 2) wait for producer (hides the LDG latency when ahead)
            if (tid < 32) {
                while (ld_acquire_gpu(fp) <= c) { }
                u_sh[c * 32 + tid] = ldcg_f32(g_u + a * LXN + c * 32 + tid);
            }
            __syncthreads();
            // 3) compute purely from registers
#pragma unroll
            for (int k = 0; k < 32; ++k) {
                r = fmaf(r, mem, v[k] * u_sh[c * 32 + k]);
                tbuf[l * 33 + k] = tanh_fast(r * c2);
            }
            __syncwarp();
            // 4) coalesced streaming stores via per-warp transpose
            unsigned ob = tbase + (unsigned)(c * 32);
#pragma unroll 8
            for (int row = 0; row < 32; ++row)
                stcs_f32(out + ob + (unsigned)row * 513u, tbuf[row * 33 + l]);
            __syncwarp();
        }
    }
}

// ---------------------------------------------------------------------------
extern "C" void kernel_launch(void* const* d_in, const int* in_sizes, int n_in,
                              void* d_out, int out_size) {
    const int*   lx    = (const int*)  d_in[0];
    const float* TM    = (const float*)d_in[1];
    const float* diff  = (const float*)d_in[2];
    const float* eff   = (const float*)d_in[3];
    const float* mem   = (const float*)d_in[4];
    const float* boost = (const float*)d_in[5];
    float* out = (float*)d_out;

    build_G<<<LXN, LXN>>>(lx, TM);
    fused<<<NALGOS + NALGOS * 4, 256>>>(lx, diff, eff, mem, boost, TM, out);
}